// round 3
// baseline (speedup 1.0000x reference)
#include <cuda_runtime.h>

// Problem constants: B=16, H=8, N=64, L=64, DK=64
// attn = softmax(mask ? QK^T/8 : -32768) ; out = attn @ V
// 8192 independent 64x64x64 fp32 attention tiles.

#define NBLOCKS 8192
#define TEMP_INV 0.125f
#define MASK_FILL_F (-32768.0f)

// ---- packed f32x2 helpers (sm_100+ PTX) ----
__device__ __forceinline__ void fma2(unsigned long long& d,
                                     unsigned long long a,
                                     unsigned long long b) {
    asm("fma.rn.f32x2 %0, %1, %2, %0;" : "+l"(d) : "l"(a), "l"(b));
}
__device__ __forceinline__ unsigned long long pack2(float x, float y) {
    unsigned long long r;
    asm("mov.b64 %0, {%1, %2};" : "=l"(r) : "f"(x), "f"(y));
    return r;
}
__device__ __forceinline__ void unpack2(unsigned long long v, float& x, float& y) {
    asm("mov.b64 {%0, %1}, %2;" : "=f"(x), "=f"(y) : "l"(v));
}

// Swizzled shared index: row-major 64x64 floats, 16B granules XORed with row
// low bits so strided row accesses spread across banks.
__device__ __forceinline__ int sidx(int row, int col) {
    return (row << 6) + ((((col >> 2) ^ (row & 7)) << 2) | (col & 3));
}

__global__ void __launch_bounds__(256)
attn_kernel(const float* __restrict__ q, const float* __restrict__ k,
            const float* __restrict__ v, const int* __restrict__ mask,
            float* __restrict__ out) {
    __shared__ float Qs[64 * 64];
    __shared__ float Ks[64 * 64];
    __shared__ float Vs[64 * 64];

    const int bid = blockIdx.x;
    const size_t base = (size_t)bid << 12;           // bid * 64*64
    const int* mbase = mask + ((size_t)(bid >> 9) << 12);  // b = bid/(H*N)

    const int tid = threadIdx.x;
    const int ty = tid >> 4;   // 0..15 -> rows ty + 16*i
    const int tx = tid & 15;   // 0..15 -> GEMM1 cols tx + 16*j

    // ---- stage Q, K, V into swizzled smem (float4, conflict-free) ----
    {
        const float4* qg = (const float4*)(q + base);
        const float4* kg = (const float4*)(k + base);
        const float4* vg = (const float4*)(v + base);
        float4* Qs4 = (float4*)Qs;
        float4* Ks4 = (float4*)Ks;
        float4* Vs4 = (float4*)Vs;
#pragma unroll
        for (int e = tid; e < 1024; e += 256) {
            int row = e >> 4;
            int dv = e & 15;
            int si = (row << 4) + (dv ^ (row & 7));
            Qs4[si] = qg[e];
            Ks4[si] = kg[e];
            Vs4[si] = vg[e];
        }
    }

    // ---- prefetch mask (L2-resident, 16 loads in flight across GEMM1) ----
    int mreg[4][4];
#pragma unroll
    for (int i = 0; i < 4; i++) {
        int row = ty + 16 * i;
#pragma unroll
        for (int j = 0; j < 4; j++)
            mreg[i][j] = __ldg(&mbase[(row << 6) + tx + 16 * j]);
    }

    __syncthreads();

    // ---- GEMM1: S = Q K^T, accumulators packed over d-pairs ----
    unsigned long long acc[4][4];
#pragma unroll
    for (int i = 0; i < 4; i++)
#pragma unroll
        for (int j = 0; j < 4; j++) acc[i][j] = 0ULL;  // {0.f, 0.f}

#pragma unroll 8
    for (int d0 = 0; d0 < 64; d0 += 2) {
        unsigned long long qa[4], kb[4];
#pragma unroll
        for (int i = 0; i < 4; i++)
            qa[i] = *(const unsigned long long*)&Qs[sidx(ty + 16 * i, d0)];
#pragma unroll
        for (int j = 0; j < 4; j++)
            kb[j] = *(const unsigned long long*)&Ks[sidx(tx + 16 * j, d0)];
#pragma unroll
        for (int i = 0; i < 4; i++)
#pragma unroll
            for (int j = 0; j < 4; j++) fma2(acc[i][j], qa[i], kb[j]);
    }

    // ---- epilogue1: mask + scale, register softmax ----
    float p[4][4];
#pragma unroll
    for (int i = 0; i < 4; i++) {
#pragma unroll
        for (int j = 0; j < 4; j++) {
            float lo, hi;
            unpack2(acc[i][j], lo, hi);
            float s = lo + hi;
            p[i][j] = (mreg[i][j] != 0) ? s * TEMP_INV : MASK_FILL_F;
        }
        // row softmax across the 16 lanes sharing this ty (plus 4 local cols)
        float mx = fmaxf(fmaxf(p[i][0], p[i][1]), fmaxf(p[i][2], p[i][3]));
#pragma unroll
        for (int o = 8; o >= 1; o >>= 1)
            mx = fmaxf(mx, __shfl_xor_sync(0xffffffffu, mx, o));
        float sm = 0.0f;
#pragma unroll
        for (int j = 0; j < 4; j++) {
            p[i][j] = __expf(p[i][j] - mx);
            sm += p[i][j];
        }
#pragma unroll
        for (int o = 8; o >= 1; o >>= 1)
            sm += __shfl_xor_sync(0xffffffffu, sm, o);
        float r = __fdividef(1.0f, sm);
#pragma unroll
        for (int j = 0; j < 4; j++) p[i][j] *= r;
    }

    // ---- stage P into smem (reuse Qs) ----
    __syncthreads();  // everyone done reading Q
#pragma unroll
    for (int i = 0; i < 4; i++)
#pragma unroll
        for (int j = 0; j < 4; j++)
            Qs[sidx(ty + 16 * i, tx + 16 * j)] = p[i][j];
    __syncthreads();

    // ---- GEMM2: O = P V, accumulators packed over output col-pairs ----
    // thread cols: {2tx, 2tx+1} and {2tx+32, 2tx+33}
    unsigned long long o2[4][2];
#pragma unroll
    for (int i = 0; i < 4; i++) {
        o2[i][0] = 0ULL;
        o2[i][1] = 0ULL;
    }

#pragma unroll 4
    for (int j0 = 0; j0 < 64; j0 += 4) {
        float4 pv[4];
#pragma unroll
        for (int i = 0; i < 4; i++)
            pv[i] = *(const float4*)&Qs[sidx(ty + 16 * i, j0)];
#pragma unroll
        for (int jj = 0; jj < 4; jj++) {
            int j = j0 + jj;
            unsigned long long vb0 =
                *(const unsigned long long*)&Vs[sidx(j, 2 * tx)];
            unsigned long long vb1 =
                *(const unsigned long long*)&Vs[sidx(j, 2 * tx + 32)];
#pragma unroll
            for (int i = 0; i < 4; i++) {
                float pij = (jj == 0) ? pv[i].x
                          : (jj == 1) ? pv[i].y
                          : (jj == 2) ? pv[i].z
                                      : pv[i].w;
                unsigned long long pa = pack2(pij, pij);
                fma2(o2[i][0], pa, vb0);
                fma2(o2[i][1], pa, vb1);
            }
        }
    }

    // ---- store O (coalesced 8B stores) ----
#pragma unroll
    for (int i = 0; i < 4; i++) {
        int row = ty + 16 * i;
        float* orow = out + base + ((size_t)row << 6);
        *(unsigned long long*)&orow[2 * tx] = o2[i][0];
        *(unsigned long long*)&orow[2 * tx + 32] = o2[i][1];
    }
}

extern "C" void kernel_launch(void* const* d_in, const int* in_sizes, int n_in,
                              void* d_out, int out_size) {
    const float* q = (const float*)d_in[0];
    const float* k = (const float*)d_in[1];
    const float* v = (const float*)d_in[2];
    const int* mask = (const int*)d_in[3];
    float* out = (float*)d_out;
    attn_kernel<<<NBLOCKS, 256>>>(q, k, v, mask, out);
}

// round 4
// speedup vs baseline: 1.6105x; 1.6105x over previous
#include <cuda_runtime.h>

// Problem constants: B=16, H=8, N=64, L=64, DK=64
// attn = softmax(mask ? QK^T/8 : -32768) ; out = attn @ V
// 8192 independent 64x64x64 fp32 attention tiles.

#define NBLOCKS 8192
#define TEMP_INV 0.125f
#define MASK_FILL_F (-32768.0f)

// ---- packed f32x2 helpers (sm_100+ PTX) ----
__device__ __forceinline__ void fma2(unsigned long long& d,
                                     unsigned long long a,
                                     unsigned long long b) {
    asm("fma.rn.f32x2 %0, %1, %2, %0;" : "+l"(d) : "l"(a), "l"(b));
}
__device__ __forceinline__ unsigned long long pack2(float x, float y) {
    unsigned long long r;
    asm("mov.b64 %0, {%1, %2};" : "=l"(r) : "f"(x), "f"(y));
    return r;
}
__device__ __forceinline__ void unpack2(unsigned long long v, float& x, float& y) {
    asm("mov.b64 {%0, %1}, %2;" : "=f"(x), "=f"(y) : "l"(v));
}

// Swizzled shared index: row-major 64x64 floats, 16B granules XORed with row
// low bits so strided row accesses spread across banks.
__device__ __forceinline__ int sidx(int row, int col) {
    return (row << 6) + ((((col >> 2) ^ (row & 7)) << 2) | (col & 3));
}

__global__ void __launch_bounds__(256)
attn_kernel(const float* __restrict__ q, const float* __restrict__ k,
            const float* __restrict__ v, const int* __restrict__ mask,
            float* __restrict__ out) {
    __shared__ float Qs[64 * 64];
    __shared__ float Ks[64 * 64];
    __shared__ float Vs[64 * 64];

    const int bid = blockIdx.x;
    const size_t base = (size_t)bid << 12;           // bid * 64*64
    const int* mbase = mask + ((size_t)(bid >> 9) << 12);  // b = bid/(H*N)

    const int tid = threadIdx.x;
    const int ty = tid >> 4;   // 0..15 -> rows ty + 16*i
    const int tx = tid & 15;   // 0..15 -> GEMM1 cols tx + 16*j

    // ---- stage Q, K, V into swizzled smem (float4, conflict-free) ----
    {
        const float4* qg = (const float4*)(q + base);
        const float4* kg = (const float4*)(k + base);
        const float4* vg = (const float4*)(v + base);
        float4* Qs4 = (float4*)Qs;
        float4* Ks4 = (float4*)Ks;
        float4* Vs4 = (float4*)Vs;
#pragma unroll
        for (int e = tid; e < 1024; e += 256) {
            int row = e >> 4;
            int dv = e & 15;
            int si = (row << 4) + (dv ^ (row & 7));
            Qs4[si] = qg[e];
            Ks4[si] = kg[e];
            Vs4[si] = vg[e];
        }
    }

    // ---- prefetch mask (L2-resident, 16 loads in flight across GEMM1) ----
    int mreg[4][4];
#pragma unroll
    for (int i = 0; i < 4; i++) {
        int row = ty + 16 * i;
#pragma unroll
        for (int j = 0; j < 4; j++)
            mreg[i][j] = __ldg(&mbase[(row << 6) + tx + 16 * j]);
    }

    __syncthreads();

    // ---- GEMM1: S = Q K^T, accumulators packed over d-pairs ----
    unsigned long long acc[4][4];
#pragma unroll
    for (int i = 0; i < 4; i++)
#pragma unroll
        for (int j = 0; j < 4; j++) acc[i][j] = 0ULL;  // {0.f, 0.f}

#pragma unroll 8
    for (int d0 = 0; d0 < 64; d0 += 2) {
        unsigned long long qa[4], kb[4];
#pragma unroll
        for (int i = 0; i < 4; i++)
            qa[i] = *(const unsigned long long*)&Qs[sidx(ty + 16 * i, d0)];
#pragma unroll
        for (int j = 0; j < 4; j++)
            kb[j] = *(const unsigned long long*)&Ks[sidx(tx + 16 * j, d0)];
#pragma unroll
        for (int i = 0; i < 4; i++)
#pragma unroll
            for (int j = 0; j < 4; j++) fma2(acc[i][j], qa[i], kb[j]);
    }

    // ---- epilogue1: mask + scale, register softmax ----
    float p[4][4];
#pragma unroll
    for (int i = 0; i < 4; i++) {
#pragma unroll
        for (int j = 0; j < 4; j++) {
            float lo, hi;
            unpack2(acc[i][j], lo, hi);
            float s = lo + hi;
            p[i][j] = (mreg[i][j] != 0) ? s * TEMP_INV : MASK_FILL_F;
        }
        // row softmax across the 16 lanes sharing this ty (plus 4 local cols)
        float mx = fmaxf(fmaxf(p[i][0], p[i][1]), fmaxf(p[i][2], p[i][3]));
#pragma unroll
        for (int o = 8; o >= 1; o >>= 1)
            mx = fmaxf(mx, __shfl_xor_sync(0xffffffffu, mx, o));
        float sm = 0.0f;
#pragma unroll
        for (int j = 0; j < 4; j++) {
            p[i][j] = __expf(p[i][j] - mx);
            sm += p[i][j];
        }
#pragma unroll
        for (int o = 8; o >= 1; o >>= 1)
            sm += __shfl_xor_sync(0xffffffffu, sm, o);
        float r = __fdividef(1.0f, sm);
#pragma unroll
        for (int j = 0; j < 4; j++) p[i][j] *= r;
    }

    // ---- stage P into smem (reuse Qs) ----
    __syncthreads();  // everyone done reading Q
#pragma unroll
    for (int i = 0; i < 4; i++)
#pragma unroll
        for (int j = 0; j < 4; j++)
            Qs[sidx(ty + 16 * i, tx + 16 * j)] = p[i][j];
    __syncthreads();

    // ---- GEMM2: O = P V, accumulators packed over output col-pairs ----
    // thread cols: {2tx, 2tx+1} and {2tx+32, 2tx+33}
    unsigned long long o2[4][2];
#pragma unroll
    for (int i = 0; i < 4; i++) {
        o2[i][0] = 0ULL;
        o2[i][1] = 0ULL;
    }

#pragma unroll 4
    for (int j0 = 0; j0 < 64; j0 += 4) {
        float4 pv[4];
#pragma unroll
        for (int i = 0; i < 4; i++)
            pv[i] = *(const float4*)&Qs[sidx(ty + 16 * i, j0)];
#pragma unroll
        for (int jj = 0; jj < 4; jj++) {
            int j = j0 + jj;
            unsigned long long vb0 =
                *(const unsigned long long*)&Vs[sidx(j, 2 * tx)];
            unsigned long long vb1 =
                *(const unsigned long long*)&Vs[sidx(j, 2 * tx + 32)];
#pragma unroll
            for (int i = 0; i < 4; i++) {
                float pij = (jj == 0) ? pv[i].x
                          : (jj == 1) ? pv[i].y
                          : (jj == 2) ? pv[i].z
                                      : pv[i].w;
                unsigned long long pa = pack2(pij, pij);
                fma2(o2[i][0], pa, vb0);
                fma2(o2[i][1], pa, vb1);
            }
        }
    }

    // ---- store O (coalesced 8B stores) ----
#pragma unroll
    for (int i = 0; i < 4; i++) {
        int row = ty + 16 * i;
        float* orow = out + base + ((size_t)row << 6);
        *(unsigned long long*)&orow[2 * tx] = o2[i][0];
        *(unsigned long long*)&orow[2 * tx + 32] = o2[i][1];
    }
}

extern "C" void kernel_launch(void* const* d_in, const int* in_sizes, int n_in,
                              void* d_out, int out_size) {
    const float* q = (const float*)d_in[0];
    const float* k = (const float*)d_in[1];
    const float* v = (const float*)d_in[2];
    const int* mask = (const int*)d_in[3];
    float* out = (float*)d_out;
    attn_kernel<<<NBLOCKS, 256>>>(q, k, v, mask, out);
}